// round 6
// baseline (speedup 1.0000x reference)
#include <cuda_runtime.h>
#include <cuda_bf16.h>
#include <math.h>
#include <stdint.h>

// ---------------------------------------------------------------------------
// HermitianAttention (B=2,S=2048,D=1024,H=16,hd=64) — bf16x3, pre-packed.
// R6: GEMM 256 threads / 8 warps (warp tile 32x64) + fused QKV launch.
// ---------------------------------------------------------------------------

#define BATCH 2
#define SEQ   2048
#define DIMM  1024
#define NH    16
#define HD    64
#define NTOK  (BATCH * SEQ)
#define NTD   (NTOK * DIMM)
#define KP    1024              // k-pairs of the stacked K=2048
#define ATT_SCALE 0.125f

#define MEGA (1024u * 1024u)
__device__ uint32_t g_scratch[56u * MEGA];

__device__ __forceinline__ void cvt2(float x0, float x1, uint32_t& h, uint32_t& l) {
    __nv_bfloat16 h0 = __float2bfloat16_rn(x0);
    __nv_bfloat16 h1 = __float2bfloat16_rn(x1);
    float r0 = x0 - __bfloat162float(h0);
    float r1 = x1 - __bfloat162float(h1);
    __nv_bfloat16 l0 = __float2bfloat16_rn(r0);
    __nv_bfloat16 l1 = __float2bfloat16_rn(r1);
    h = ((uint32_t)__bfloat16_as_ushort(h1) << 16) | __bfloat16_as_ushort(h0);
    l = ((uint32_t)__bfloat16_as_ushort(l1) << 16) | __bfloat16_as_ushort(l0);
}

__device__ __forceinline__ void mma16(float c[4], const uint32_t a[4], const uint32_t b[2]) {
    asm volatile(
        "mma.sync.aligned.m16n8k16.row.col.f32.bf16.bf16.f32 "
        "{%0,%1,%2,%3}, {%4,%5,%6,%7}, {%8,%9}, {%0,%1,%2,%3};\n"
        : "+f"(c[0]), "+f"(c[1]), "+f"(c[2]), "+f"(c[3])
        : "r"(a[0]), "r"(a[1]), "r"(a[2]), "r"(a[3]), "r"(b[0]), "r"(b[1]));
}

__device__ __forceinline__ void cpa16(void* dst, const void* src) {
    uint32_t d = (uint32_t)__cvta_generic_to_shared(dst);
    asm volatile("cp.async.cg.shared.global [%0], [%1], 16;\n" :: "r"(d), "l"(src));
}
#define CP_COMMIT() asm volatile("cp.async.commit_group;\n" ::: "memory")

// ---------------------------------------------------------------------------
// Pack kernels (one-time, memory-bound).
// ---------------------------------------------------------------------------
__global__ void pack_x(const float* __restrict__ zr, const float* __restrict__ zi,
                       uint32_t* __restrict__ Ah, uint32_t* __restrict__ Al)
{
    int p = blockIdx.x * blockDim.x + threadIdx.x;
    int m = p >> 10, j = p & 1023;
    const float* src = (j < 512) ? zr : zi;
    int c = (j < 512) ? (j * 2) : ((j - 512) * 2);
    float2 v = *(const float2*)(src + (size_t)m * DIMM + c);
    uint32_t h, l; cvt2(v.x, v.y, h, l);
    Ah[p] = h; Al[p] = l;
}

__global__ void pack_w(const float* __restrict__ Wr, const float* __restrict__ Wi,
                       uint32_t* __restrict__ Bh, uint32_t* __restrict__ Bl)
{
    int idx = blockIdx.x * blockDim.x + threadIdx.x;
    int p = idx >> 11, n = idx & 2047;
    int k0 = 2 * p;
    float a, b;
    if (p < 512) {
        if (n < 1024) {
            a = Wr[(size_t)k0 * DIMM + n];   b = Wr[(size_t)(k0 + 1) * DIMM + n];
        } else {
            int nn = n - 1024;
            a = Wi[(size_t)k0 * DIMM + nn];  b = Wi[(size_t)(k0 + 1) * DIMM + nn];
        }
    } else {
        int kk = k0 - 1024;
        if (n < 1024) {
            a = -Wi[(size_t)kk * DIMM + n];  b = -Wi[(size_t)(kk + 1) * DIMM + n];
        } else {
            int nn = n - 1024;
            a = Wr[(size_t)kk * DIMM + nn];  b = Wr[(size_t)(kk + 1) * DIMM + nn];
        }
    }
    uint32_t h, l; cvt2(a, b, h, l);
    Bh[idx] = h; Bl[idx] = l;
}

// ---------------------------------------------------------------------------
// bf16x3 GEMM body. M=4096, Kpairs=1024, N=2048. BM=BN=128, 16 kpairs/stage,
// 2-stage cp.async. 256 threads, 8 warps (4M x 2N), warp tile 32x64.
// ---------------------------------------------------------------------------
struct GSmem {
    uint32_t Ah[2][128][20], Al[2][128][20];
    uint32_t Bh[2][16][136], Bl[2][16][136];
};

__device__ __forceinline__ void
gemm_body(GSmem& sm,
          const uint32_t* __restrict__ Ah, const uint32_t* __restrict__ Al,
          const uint32_t* __restrict__ Bh, const uint32_t* __restrict__ Bl,
          uint32_t* __restrict__ Yh, uint32_t* __restrict__ Yl,
          float* __restrict__ Y0, float* __restrict__ Y1, bool pack_out)
{
    const int tid = threadIdx.x;
    const int w = tid >> 5, lane = tid & 31;
    const int grp = lane >> 2, tk = lane & 3;
    const int warpM = (w >> 1) * 32;     // 0,32,64,96
    const int warpN = (w & 1) * 64;      // 0,64
    const int bm = blockIdx.y * 128;
    const int bn = blockIdx.x * 128;

    float acc[2][8][4];
    #pragma unroll
    for (int mi = 0; mi < 2; mi++)
        #pragma unroll
        for (int ni = 0; ni < 8; ni++)
            #pragma unroll
            for (int v = 0; v < 4; v++) acc[mi][ni][v] = 0.0f;

    auto fill = [&](int s, int kp) {
        #pragma unroll
        for (int it = 0; it < 4; it++) {
            int task = tid + it * 256;          // 0..1023
            int t2 = task & 511;
            int r = t2 >> 2, c = (t2 & 3) * 4;
            const uint32_t* src = (task < 512 ? Ah : Al) + (size_t)(bm + r) * KP + kp + c;
            if (task < 512) cpa16(&sm.Ah[s][r][c], src);
            else            cpa16(&sm.Al[s][r][c], src);
        }
        #pragma unroll
        for (int it = 0; it < 4; it++) {
            int task = tid + it * 256;
            int t2 = task & 511;
            int p = t2 >> 5, c = (t2 & 31) * 4;
            const uint32_t* src = (task < 512 ? Bh : Bl) + (size_t)(kp + p) * 2048 + bn + c;
            if (task < 512) cpa16(&sm.Bh[s][p][c], src);
            else            cpa16(&sm.Bl[s][p][c], src);
        }
    };

    fill(0, 0);
    CP_COMMIT();

    for (int st = 0; st < 64; st++) {
        int cur = st & 1;
        if (st + 1 < 64) {
            fill(cur ^ 1, (st + 1) * 16);
            CP_COMMIT();
            asm volatile("cp.async.wait_group 1;\n" ::: "memory");
        } else {
            asm volatile("cp.async.wait_group 0;\n" ::: "memory");
        }
        __syncthreads();

        #pragma unroll
        for (int kk = 0; kk < 2; kk++) {
            uint32_t afh[2][4], afl[2][4];
            #pragma unroll
            for (int mi = 0; mi < 2; mi++) {
                int m0 = warpM + mi * 16;
                afh[mi][0] = sm.Ah[cur][m0 + grp    ][kk * 8 + tk    ];
                afh[mi][1] = sm.Ah[cur][m0 + grp + 8][kk * 8 + tk    ];
                afh[mi][2] = sm.Ah[cur][m0 + grp    ][kk * 8 + tk + 4];
                afh[mi][3] = sm.Ah[cur][m0 + grp + 8][kk * 8 + tk + 4];
                afl[mi][0] = sm.Al[cur][m0 + grp    ][kk * 8 + tk    ];
                afl[mi][1] = sm.Al[cur][m0 + grp + 8][kk * 8 + tk    ];
                afl[mi][2] = sm.Al[cur][m0 + grp    ][kk * 8 + tk + 4];
                afl[mi][3] = sm.Al[cur][m0 + grp + 8][kk * 8 + tk + 4];
            }
            #pragma unroll
            for (int ni = 0; ni < 8; ni++) {
                int n0 = warpN + ni * 8;
                uint32_t bfh[2], bfl[2];
                bfh[0] = sm.Bh[cur][kk * 8 + tk    ][n0 + grp];
                bfh[1] = sm.Bh[cur][kk * 8 + tk + 4][n0 + grp];
                bfl[0] = sm.Bl[cur][kk * 8 + tk    ][n0 + grp];
                bfl[1] = sm.Bl[cur][kk * 8 + tk + 4][n0 + grp];
                #pragma unroll
                for (int mi = 0; mi < 2; mi++) {
                    mma16(acc[mi][ni], afh[mi], bfh);
                    mma16(acc[mi][ni], afh[mi], bfl);
                    mma16(acc[mi][ni], afl[mi], bfh);
                }
            }
        }
        __syncthreads();
    }

    if (pack_out) {
        #pragma unroll
        for (int mi = 0; mi < 2; mi++) {
            int m = bm + warpM + mi * 16 + grp;
            #pragma unroll
            for (int ni = 0; ni < 8; ni++) {
                int n = bn + warpN + ni * 8 + tk * 2;
                uint32_t h, l;
                cvt2(acc[mi][ni][0], acc[mi][ni][1], h, l);
                Yh[(size_t)m * KP + (n >> 1)] = h;
                Yl[(size_t)m * KP + (n >> 1)] = l;
                cvt2(acc[mi][ni][2], acc[mi][ni][3], h, l);
                Yh[(size_t)(m + 8) * KP + (n >> 1)] = h;
                Yl[(size_t)(m + 8) * KP + (n >> 1)] = l;
            }
        }
    } else {
        #pragma unroll
        for (int mi = 0; mi < 2; mi++) {
            int m = bm + warpM + mi * 16 + grp;
            #pragma unroll
            for (int ni = 0; ni < 8; ni++) {
                int n = bn + warpN + ni * 8 + tk * 2;
                float* base; int nn;
                if (n < DIMM) { base = Y0; nn = n; } else { base = Y1; nn = n - DIMM; }
                *(float2*)(base + (size_t)m * DIMM + nn) =
                    make_float2(acc[mi][ni][0], acc[mi][ni][1]);
                *(float2*)(base + (size_t)(m + 8) * DIMM + nn) =
                    make_float2(acc[mi][ni][2], acc[mi][ni][3]);
            }
        }
    }
}

// Fused QKV: grid.z selects weight/output set.
__global__ void __launch_bounds__(256, 1)
gemm_qkv(const uint32_t* __restrict__ Ah, const uint32_t* __restrict__ Al,
         const uint32_t* __restrict__ Bqh, const uint32_t* __restrict__ Bql,
         const uint32_t* __restrict__ Bkh, const uint32_t* __restrict__ Bkl,
         const uint32_t* __restrict__ Bvh, const uint32_t* __restrict__ Bvl,
         uint32_t* __restrict__ Qh, uint32_t* __restrict__ Ql,
         uint32_t* __restrict__ Kh, uint32_t* __restrict__ Kl,
         uint32_t* __restrict__ Vh, uint32_t* __restrict__ Vl)
{
    __shared__ GSmem sm;
    const uint32_t *Bh, *Bl; uint32_t *Yh, *Yl;
    if (blockIdx.z == 0)      { Bh = Bqh; Bl = Bql; Yh = Qh; Yl = Ql; }
    else if (blockIdx.z == 1) { Bh = Bkh; Bl = Bkl; Yh = Kh; Yl = Kl; }
    else                      { Bh = Bvh; Bl = Bvl; Yh = Vh; Yl = Vl; }
    gemm_body(sm, Ah, Al, Bh, Bl, Yh, Yl, nullptr, nullptr, true);
}

__global__ void __launch_bounds__(256, 1)
gemm_o(const uint32_t* __restrict__ Ah, const uint32_t* __restrict__ Al,
       const uint32_t* __restrict__ Bh, const uint32_t* __restrict__ Bl,
       float* __restrict__ Y0, float* __restrict__ Y1)
{
    __shared__ GSmem sm;
    gemm_body(sm, Ah, Al, Bh, Bl, nullptr, nullptr, Y0, Y1, false);
}

// ---------------------------------------------------------------------------
// Flash attention bf16x3 on pre-packed q/k/v (unchanged from R5).
// ---------------------------------------------------------------------------
struct FSmem {
    uint32_t Qh[128][68], Ql[128][68];
    uint32_t Kh[64][68],  Kl[64][68];
    uint32_t Vh[32][136], Vl[32][136];
    uint32_t Ph[128][36], Pl[128][36];
    float S[128][68];
    float M[128], L[128], Al[128];
};

__global__ void __launch_bounds__(256, 1)
flash_bf16x3(const uint32_t* __restrict__ Qph, const uint32_t* __restrict__ Qpl,
             const uint32_t* __restrict__ Kph, const uint32_t* __restrict__ Kpl,
             const uint32_t* __restrict__ Vph, const uint32_t* __restrict__ Vpl,
             uint32_t* __restrict__ Aoh, uint32_t* __restrict__ Aol)
{
    extern __shared__ char raw[];
    FSmem& s = *reinterpret_cast<FSmem*>(raw);

    const int tid = threadIdx.x;
    const int w = tid >> 5, lane = tid & 31;
    const int grp = lane >> 2, tk = lane & 3;
    const int warpM = w >> 1;
    const int warpN = w & 1;
    const int bh = blockIdx.y;
    const int b = bh >> 4, h = bh & 15;
    const int qt = blockIdx.x;
    const size_t tokb = (size_t)b * SEQ;
    const int cph = h * 32;
    const int colr = h * HD;

    #pragma unroll
    for (int it = 0; it < 16; it++) {
        int task = tid + it * 256;
        int t2 = task & 2047;
        int r = t2 >> 4, cj = t2 & 15;
        int jj = (cj < 8) ? (cph + cj * 4) : (512 + cph + (cj - 8) * 4);
        const uint32_t* src = (task < 2048 ? Qph : Qpl) + (tokb + qt * 128 + r) * KP + jj;
        uint4 v = *(const uint4*)src;
        uint32_t* dst = (task < 2048) ? &s.Qh[r][cj * 4] : &s.Ql[r][cj * 4];
        dst[0] = v.x; dst[1] = v.y; dst[2] = v.z; dst[3] = v.w;
    }
    if (tid < 128) { s.M[tid] = -1e30f; s.L[tid] = 0.0f; }

    float o[2][8][4];
    #pragma unroll
    for (int mi = 0; mi < 2; mi++)
        #pragma unroll
        for (int ni = 0; ni < 8; ni++)
            #pragma unroll
            for (int v = 0; v < 4; v++) o[mi][ni][v] = 0.0f;

    __syncthreads();

    for (int kt = 0; kt < SEQ / 64; kt++) {
        #pragma unroll
        for (int it = 0; it < 8; it++) {
            int task = tid + it * 256;
            int t2 = task & 1023;
            int r = t2 >> 4, cj = t2 & 15;
            int jj = (cj < 8) ? (cph + cj * 4) : (512 + cph + (cj - 8) * 4);
            const uint32_t* src = (task < 1024 ? Kph : Kpl) + (tokb + kt * 64 + r) * KP + jj;
            uint4 v = *(const uint4*)src;
            uint32_t* dst = (task < 1024) ? &s.Kh[r][cj * 4] : &s.Kl[r][cj * 4];
            dst[0] = v.x; dst[1] = v.y; dst[2] = v.z; dst[3] = v.w;
        }
        #pragma unroll
        for (int it = 0; it < 4; it++) {
            int task = tid + it * 256;
            int t2 = task & 511;
            int p = t2 >> 4, cj = t2 & 15;
            int jj = (cj < 8) ? (cph + cj * 4) : (512 + cph + (cj - 8) * 4);
            int db = (cj < 8) ? (cj * 8) : (64 + (cj - 8) * 8);
            const uint32_t* base = (task < 512) ? Vph : Vpl;
            const uint32_t* r0 = base + (tokb + kt * 64 + 2 * p) * KP + jj;
            uint4 a4 = *(const uint4*)r0;
            uint4 b4 = *(const uint4*)(r0 + KP);
            uint32_t* dst = (task < 512) ? &s.Vh[p][db] : &s.Vl[p][db];
            dst[0] = __byte_perm(a4.x, b4.x, 0x5410);
            dst[1] = __byte_perm(a4.x, b4.x, 0x7632);
            dst[2] = __byte_perm(a4.y, b4.y, 0x5410);
            dst[3] = __byte_perm(a4.y, b4.y, 0x7632);
            dst[4] = __byte_perm(a4.z, b4.z, 0x5410);
            dst[5] = __byte_perm(a4.z, b4.z, 0x7632);
            dst[6] = __byte_perm(a4.w, b4.w, 0x5410);
            dst[7] = __byte_perm(a4.w, b4.w, 0x7632);
        }
        __syncthreads();

        {
            float sc[2][4][4];
            #pragma unroll
            for (int mi = 0; mi < 2; mi++)
                #pragma unroll
                for (int ni = 0; ni < 4; ni++)
                    #pragma unroll
                    for (int v = 0; v < 4; v++) sc[mi][ni][v] = 0.0f;

            #pragma unroll
            for (int kk = 0; kk < 8; kk++) {
                uint32_t afh[2][4], afl[2][4];
                #pragma unroll
                for (int mi = 0; mi < 2; mi++) {
                    int m0 = warpM * 32 + mi * 16;
                    afh[mi][0] = s.Qh[m0 + grp    ][kk * 8 + tk    ];
                    afh[mi][1] = s.Qh[m0 + grp + 8][kk * 8 + tk    ];
                    afh[mi][2] = s.Qh[m0 + grp    ][kk * 8 + tk + 4];
                    afh[mi][3] = s.Qh[m0 + grp + 8][kk * 8 + tk + 4];
                    afl[mi][0] = s.Ql[m0 + grp    ][kk * 8 + tk    ];
                    afl[mi][1] = s.Ql[m0 + grp + 8][kk * 8 + tk    ];
                    afl[mi][2] = s.Ql[m0 + grp    ][kk * 8 + tk + 4];
                    afl[mi][3] = s.Ql[m0 + grp + 8][kk * 8 + tk + 4];
                }
                #pragma unroll
                for (int ni = 0; ni < 4; ni++) {
                    int n0 = warpN * 32 + ni * 8;
                    uint32_t bfh[2], bfl[2];
                    bfh[0] = s.Kh[n0 + grp][kk * 8 + tk    ];
                    bfh[1] = s.Kh[n0 + grp][kk * 8 + tk + 4];
                    bfl[0] = s.Kl[n0 + grp][kk * 8 + tk    ];
                    bfl[1] = s.Kl[n0 + grp][kk * 8 + tk + 4];
                    #pragma unroll
                    for (int mi = 0; mi < 2; mi++) {
                        mma16(sc[mi][ni], afh[mi], bfh);
                        mma16(sc[mi][ni], afh[mi], bfl);
                        mma16(sc[mi][ni], afl[mi], bfh);
                    }
                }
            }
            #pragma unroll
            for (int mi = 0; mi < 2; mi++) {
                int rr = warpM * 32 + mi * 16 + grp;
                #pragma unroll
                for (int ni = 0; ni < 4; ni++) {
                    int cc = warpN * 32 + ni * 8 + tk * 2;
                    *(float2*)&s.S[rr][cc] =
                        make_float2(sc[mi][ni][0] * ATT_SCALE, sc[mi][ni][1] * ATT_SCALE);
                    *(float2*)&s.S[rr + 8][cc] =
                        make_float2(sc[mi][ni][2] * ATT_SCALE, sc[mi][ni][3] * ATT_SCALE);
                }
            }
        }
        __syncthreads();

        {
            int rr = tid >> 1, c0 = (tid & 1) * 32;
            float mx = -1e30f;
            #pragma unroll
            for (int c = 0; c < 32; c++) mx = fmaxf(mx, s.S[rr][c0 + c]);
            mx = fmaxf(mx, __shfl_xor_sync(0xffffffffu, mx, 1));
            float mold = s.M[rr];
            float mnew = fmaxf(mold, mx);
            float ls = 0.0f;
            #pragma unroll
            for (int jp = 0; jp < 16; jp++) {
                float e0 = __expf(s.S[rr][c0 + 2 * jp    ] - mnew);
                float e1 = __expf(s.S[rr][c0 + 2 * jp + 1] - mnew);
                ls += e0 + e1;
                uint32_t hh, ll;
                cvt2(e0, e1, hh, ll);
                s.Ph[rr][c0 / 2 + jp] = hh;
                s.Pl[rr][c0 / 2 + jp] = ll;
            }
            ls += __shfl_xor_sync(0xffffffffu, ls, 1);
            if ((tid & 1) == 0) {
                float al = __expf(mold - mnew);
                s.M[rr] = mnew;
                s.Al[rr] = al;
                s.L[rr] = s.L[rr] * al + ls;
            }
        }
        __syncthreads();

        {
            #pragma unroll
            for (int mi = 0; mi < 2; mi++) {
                int r0 = warpM * 32 + mi * 16 + grp;
                float a0 = s.Al[r0], a1 = s.Al[r0 + 8];
                #pragma unroll
                for (int ni = 0; ni < 8; ni++) {
                    o[mi][ni][0] *= a0; o[mi][ni][1] *= a0;
                    o[mi][ni][2] *= a1; o[mi][ni][3] *= a1;
                }
            }
            #pragma unroll
            for (int kk = 0; kk < 4; kk++) {
                uint32_t afh[2][4], afl[2][4];
                #pragma unroll
                for (int mi = 0; mi < 2; mi++) {
                    int m0 = warpM * 32 + mi * 16;
                    afh[mi][0] = s.Ph[m0 + grp    ][kk * 8 + tk    ];
                    afh[mi][1] = s.Ph[m0 + grp + 8][kk * 8 + tk    ];
                    afh[mi][2] = s.Ph[m0 + grp    ][kk * 8 + tk + 4];
                    afh[mi][3] = s.Ph[m0 + grp + 8][kk * 8 + tk + 4];
                    afl[mi][0] = s.Pl[m0 + grp    ][kk * 8 + tk    ];
                    afl[mi][1] = s.Pl[m0 + grp + 8][kk * 8 + tk    ];
                    afl[mi][2] = s.Pl[m0 + grp    ][kk * 8 + tk + 4];
                    afl[mi][3] = s.Pl[m0 + grp + 8][kk * 8 + tk + 4];
                }
                #pragma unroll
                for (int ni = 0; ni < 8; ni++) {
                    int n0 = warpN * 64 + ni * 8;
                    uint32_t bfh[2], bfl[2];
                    bfh[0] = s.Vh[kk * 8 + tk    ][n0 + grp];
                    bfh[1] = s.Vh[kk * 8 + tk + 4][n0 + grp];
                    bfl[0] = s.Vl[kk * 8 + tk    ][n0 + grp];
                    bfl[1] = s.Vl[kk * 8 + tk + 4][n0 + grp];
                    #pragma unroll
                    for (int mi = 0; mi < 2; mi++) {
                        mma16(o[mi][ni], afh[mi], bfh);
                        mma16(o[mi][ni], afh[mi], bfl);
                        mma16(o[mi][ni], afl[mi], bfh);
                    }
                }
            }
        }
        __syncthreads();
    }

    #pragma unroll
    for (int mi = 0; mi < 2; mi++) {
        int r0 = warpM * 32 + mi * 16 + grp;
        float l0 = 1.0f / s.L[r0];
        float l1 = 1.0f / s.L[r0 + 8];
        int tok = b * SEQ + qt * 128;
        #pragma unroll
        for (int ni = 0; ni < 8; ni++) {
            int c = warpN * 64 + ni * 8 + tk * 2;
            int g = (c < HD) ? (colr + c) : (1024 + colr + (c - HD));
            int idx = g >> 1;
            uint32_t hh, ll;
            cvt2(o[mi][ni][0] * l0, o[mi][ni][1] * l0, hh, ll);
            Aoh[(size_t)(tok + r0) * KP + idx] = hh;
            Aol[(size_t)(tok + r0) * KP + idx] = ll;
            cvt2(o[mi][ni][2] * l1, o[mi][ni][3] * l1, hh, ll);
            Aoh[(size_t)(tok + r0 + 8) * KP + idx] = hh;
            Aol[(size_t)(tok + r0 + 8) * KP + idx] = ll;
        }
    }
}

// ---------------------------------------------------------------------------
extern "C" void kernel_launch(void* const* d_in, const int* in_sizes, int n_in,
                              void* d_out, int out_size)
{
    const float* zr   = (const float*)d_in[0];
    const float* zi   = (const float*)d_in[1];
    const float* wq_r = (const float*)d_in[2];
    const float* wq_i = (const float*)d_in[3];
    const float* wk_r = (const float*)d_in[4];
    const float* wk_i = (const float*)d_in[5];
    const float* wv_r = (const float*)d_in[6];
    const float* wv_i = (const float*)d_in[7];
    const float* wo_r = (const float*)d_in[8];
    const float* wo_i = (const float*)d_in[9];

    uint32_t* sc = nullptr;
    cudaGetSymbolAddress((void**)&sc, g_scratch);
    uint32_t* Azh = sc + 0u  * MEGA;
    uint32_t* Azl = sc + 4u  * MEGA;
    uint32_t* Bqh = sc + 8u  * MEGA;  uint32_t* Bql = sc + 10u * MEGA;
    uint32_t* Bkh = sc + 12u * MEGA;  uint32_t* Bkl = sc + 14u * MEGA;
    uint32_t* Bvh = sc + 16u * MEGA;  uint32_t* Bvl = sc + 18u * MEGA;
    uint32_t* Boh = sc + 20u * MEGA;  uint32_t* Bol = sc + 22u * MEGA;
    uint32_t* Qh  = sc + 24u * MEGA;  uint32_t* Ql  = sc + 28u * MEGA;
    uint32_t* Kh  = sc + 32u * MEGA;  uint32_t* Kl  = sc + 36u * MEGA;
    uint32_t* Vh  = sc + 40u * MEGA;  uint32_t* Vl  = sc + 44u * MEGA;
    uint32_t* Aoh = sc + 48u * MEGA;  uint32_t* Aol = sc + 52u * MEGA;

    float* yr = (float*)d_out;
    float* yi = (float*)d_out + NTD;

    pack_x<<<(NTOK * KP) / 256, 256>>>(zr, zi, Azh, Azl);
    pack_w<<<(KP * 2048) / 256, 256>>>(wq_r, wq_i, Bqh, Bql);
    pack_w<<<(KP * 2048) / 256, 256>>>(wk_r, wk_i, Bkh, Bkl);
    pack_w<<<(KP * 2048) / 256, 256>>>(wv_r, wv_i, Bvh, Bvl);
    pack_w<<<(KP * 2048) / 256, 256>>>(wo_r, wo_i, Boh, Bol);

    dim3 qkv_grid(2048 / 128, NTOK / 128, 3);   // (16, 32, 3)
    gemm_qkv<<<qkv_grid, 256>>>(Azh, Azl, Bqh, Bql, Bkh, Bkl, Bvh, Bvl,
                                Qh, Ql, Kh, Kl, Vh, Vl);

    static const int kSmem = (int)sizeof(FSmem);
    cudaFuncSetAttribute(flash_bf16x3, cudaFuncAttributeMaxDynamicSharedMemorySize, kSmem);
    dim3 fgrid(SEQ / 128, BATCH * NH);          // (16, 32)
    flash_bf16x3<<<fgrid, 256, kSmem>>>(Qh, Ql, Kh, Kl, Vh, Vl, Aoh, Aol);

    dim3 ogrid(2048 / 128, NTOK / 128);         // (16, 32)
    gemm_o<<<ogrid, 256>>>(Aoh, Aol, Boh, Bol, yr, yi);
}

// round 8
// speedup vs baseline: 1.2300x; 1.2300x over previous
#include <cuda_runtime.h>
#include <cuda_bf16.h>
#include <math.h>
#include <stdint.h>

// ---------------------------------------------------------------------------
// HermitianAttention (B=2,S=2048,D=1024,H=16,hd=64) — bf16x3, pre-packed.
// R8: register-resident-softmax flash (+K cp.async double buffer),
//     R5-proven GEMM body + fused QKV launch, ATT_SCALE folded into Q GEMM.
// ---------------------------------------------------------------------------

#define BATCH 2
#define SEQ   2048
#define DIMM  1024
#define NH    16
#define HD    64
#define NTOK  (BATCH * SEQ)
#define NTD   (NTOK * DIMM)
#define KP    1024              // u32 k-pairs of stacked K=2048

#define MEGA (1024u * 1024u)
__device__ uint32_t g_scratch[56u * MEGA];

__device__ __forceinline__ void cvt2(float x0, float x1, uint32_t& h, uint32_t& l) {
    __nv_bfloat16 h0 = __float2bfloat16_rn(x0);
    __nv_bfloat16 h1 = __float2bfloat16_rn(x1);
    float r0 = x0 - __bfloat162float(h0);
    float r1 = x1 - __bfloat162float(h1);
    __nv_bfloat16 l0 = __float2bfloat16_rn(r0);
    __nv_bfloat16 l1 = __float2bfloat16_rn(r1);
    h = ((uint32_t)__bfloat16_as_ushort(h1) << 16) | __bfloat16_as_ushort(h0);
    l = ((uint32_t)__bfloat16_as_ushort(l1) << 16) | __bfloat16_as_ushort(l0);
}

__device__ __forceinline__ void mma16(float c[4], const uint32_t a[4], const uint32_t b[2]) {
    asm volatile(
        "mma.sync.aligned.m16n8k16.row.col.f32.bf16.bf16.f32 "
        "{%0,%1,%2,%3}, {%4,%5,%6,%7}, {%8,%9}, {%0,%1,%2,%3};\n"
        : "+f"(c[0]), "+f"(c[1]), "+f"(c[2]), "+f"(c[3])
        : "r"(a[0]), "r"(a[1]), "r"(a[2]), "r"(a[3]), "r"(b[0]), "r"(b[1]));
}

__device__ __forceinline__ void cpa16(const void* dst, const void* src) {
    uint32_t d = (uint32_t)__cvta_generic_to_shared(dst);
    asm volatile("cp.async.cg.shared.global [%0], [%1], 16;\n" :: "r"(d), "l"(src));
}
#define CP_COMMIT() asm volatile("cp.async.commit_group;\n" ::: "memory")

// ---------------------------------------------------------------------------
// Pack kernels.
// ---------------------------------------------------------------------------
__global__ void pack_x(const float* __restrict__ zr, const float* __restrict__ zi,
                       uint32_t* __restrict__ Ah, uint32_t* __restrict__ Al)
{
    int p = blockIdx.x * blockDim.x + threadIdx.x;
    int m = p >> 10, j = p & 1023;
    const float* src = (j < 512) ? zr : zi;
    int c = (j < 512) ? (j * 2) : ((j - 512) * 2);
    float2 v = *(const float2*)(src + (size_t)m * DIMM + c);
    uint32_t h, l; cvt2(v.x, v.y, h, l);
    Ah[p] = h; Al[p] = l;
}

__global__ void pack_w(const float* __restrict__ Wr, const float* __restrict__ Wi,
                       uint32_t* __restrict__ Bh, uint32_t* __restrict__ Bl)
{
    int idx = blockIdx.x * blockDim.x + threadIdx.x;
    int p = idx >> 11, n = idx & 2047;
    int k0 = 2 * p;
    float a, b;
    if (p < 512) {
        if (n < 1024) {
            a = Wr[(size_t)k0 * DIMM + n];   b = Wr[(size_t)(k0 + 1) * DIMM + n];
        } else {
            int nn = n - 1024;
            a = Wi[(size_t)k0 * DIMM + nn];  b = Wi[(size_t)(k0 + 1) * DIMM + nn];
        }
    } else {
        int kk = k0 - 1024;
        if (n < 1024) {
            a = -Wi[(size_t)kk * DIMM + n];  b = -Wi[(size_t)(kk + 1) * DIMM + n];
        } else {
            int nn = n - 1024;
            a = Wr[(size_t)kk * DIMM + nn];  b = Wr[(size_t)(kk + 1) * DIMM + nn];
        }
    }
    uint32_t h, l; cvt2(a, b, h, l);
    Bh[idx] = h; Bl[idx] = l;
}

// ---------------------------------------------------------------------------
// bf16x3 GEMM (R5-proven). M=4096, Kpairs=1024, N=2048. BM=BN=128, BK=16 kp,
// 2-stage cp.async. 128 threads, 4 warps (2x2), warp tile 64x64.
// ---------------------------------------------------------------------------
struct GSmem {
    uint32_t Ah[2][128][20], Al[2][128][20];
    uint32_t Bh[2][16][136], Bl[2][16][136];
};

__device__ __forceinline__ void
gemm_body(GSmem& sm,
          const uint32_t* __restrict__ Ah, const uint32_t* __restrict__ Al,
          const uint32_t* __restrict__ Bh, const uint32_t* __restrict__ Bl,
          uint32_t* __restrict__ Yh, uint32_t* __restrict__ Yl,
          float* __restrict__ Y0, float* __restrict__ Y1, bool pack_out,
          float oscale)
{
    const int tid = threadIdx.x;
    const int w = tid >> 5, lane = tid & 31;
    const int grp = lane >> 2, tk = lane & 3;
    const int warpM = (w >> 1) * 64;
    const int warpN = (w & 1) * 64;
    const int bm = blockIdx.y * 128;
    const int bn = blockIdx.x * 128;

    float acc[4][8][4];
    #pragma unroll
    for (int mi = 0; mi < 4; mi++)
        #pragma unroll
        for (int ni = 0; ni < 8; ni++)
            #pragma unroll
            for (int v = 0; v < 4; v++) acc[mi][ni][v] = 0.0f;

    auto fill = [&](int s, int kp) {
        #pragma unroll
        for (int it = 0; it < 8; it++) {
            int task = tid + it * 128;          // 0..1023
            int t2 = task & 511;
            int r = t2 >> 2, c = (t2 & 3) * 4;
            const uint32_t* src = (task < 512 ? Ah : Al) + (size_t)(bm + r) * KP + kp + c;
            if (task < 512) cpa16(&sm.Ah[s][r][c], src);
            else            cpa16(&sm.Al[s][r][c], src);
        }
        #pragma unroll
        for (int it = 0; it < 8; it++) {
            int task = tid + it * 128;
            int t2 = task & 511;
            int p = t2 >> 5, c = (t2 & 31) * 4;
            const uint32_t* src = (task < 512 ? Bh : Bl) + (size_t)(kp + p) * 2048 + bn + c;
            if (task < 512) cpa16(&sm.Bh[s][p][c], src);
            else            cpa16(&sm.Bl[s][p][c], src);
        }
    };

    fill(0, 0);
    CP_COMMIT();

    for (int st = 0; st < 64; st++) {
        int cur = st & 1;
        if (st + 1 < 64) {
            fill(cur ^ 1, (st + 1) * 16);
            CP_COMMIT();
            asm volatile("cp.async.wait_group 1;\n" ::: "memory");
        } else {
            asm volatile("cp.async.wait_group 0;\n" ::: "memory");
        }
        __syncthreads();

        #pragma unroll
        for (int kk = 0; kk < 2; kk++) {
            uint32_t afh[4][4], afl[4][4];
            #pragma unroll
            for (int mi = 0; mi < 4; mi++) {
                int m0 = warpM + mi * 16;
                afh[mi][0] = sm.Ah[cur][m0 + grp    ][kk * 8 + tk    ];
                afh[mi][1] = sm.Ah[cur][m0 + grp + 8][kk * 8 + tk    ];
                afh[mi][2] = sm.Ah[cur][m0 + grp    ][kk * 8 + tk + 4];
                afh[mi][3] = sm.Ah[cur][m0 + grp + 8][kk * 8 + tk + 4];
                afl[mi][0] = sm.Al[cur][m0 + grp    ][kk * 8 + tk    ];
                afl[mi][1] = sm.Al[cur][m0 + grp + 8][kk * 8 + tk    ];
                afl[mi][2] = sm.Al[cur][m0 + grp    ][kk * 8 + tk + 4];
                afl[mi][3] = sm.Al[cur][m0 + grp + 8][kk * 8 + tk + 4];
            }
            #pragma unroll
            for (int ni = 0; ni < 8; ni++) {
                int n0 = warpN + ni * 8;
                uint32_t bfh[2], bfl[2];
                bfh[0] = sm.Bh[cur][kk * 8 + tk    ][n0 + grp];
                bfh[1] = sm.Bh[cur][kk * 8 + tk + 4][n0 + grp];
                bfl[0] = sm.Bl[cur][kk * 8 + tk    ][n0 + grp];
                bfl[1] = sm.Bl[cur][kk * 8 + tk + 4][n0 + grp];
                #pragma unroll
                for (int mi = 0; mi < 4; mi++) {
                    mma16(acc[mi][ni], afh[mi], bfh);
                    mma16(acc[mi][ni], afh[mi], bfl);
                    mma16(acc[mi][ni], afl[mi], bfh);
                }
            }
        }
        __syncthreads();
    }

    if (pack_out) {
        #pragma unroll
        for (int mi = 0; mi < 4; mi++) {
            int m = bm + warpM + mi * 16 + grp;
            #pragma unroll
            for (int ni = 0; ni < 8; ni++) {
                int n = bn + warpN + ni * 8 + tk * 2;
                uint32_t h, l;
                cvt2(acc[mi][ni][0] * oscale, acc[mi][ni][1] * oscale, h, l);
                Yh[(size_t)m * KP + (n >> 1)] = h;
                Yl[(size_t)m * KP + (n >> 1)] = l;
                cvt2(acc[mi][ni][2] * oscale, acc[mi][ni][3] * oscale, h, l);
                Yh[(size_t)(m + 8) * KP + (n >> 1)] = h;
                Yl[(size_t)(m + 8) * KP + (n >> 1)] = l;
            }
        }
    } else {
        #pragma unroll
        for (int mi = 0; mi < 4; mi++) {
            int m = bm + warpM + mi * 16 + grp;
            #pragma unroll
            for (int ni = 0; ni < 8; ni++) {
                int n = bn + warpN + ni * 8 + tk * 2;
                float* base; int nn;
                if (n < DIMM) { base = Y0; nn = n; } else { base = Y1; nn = n - DIMM; }
                *(float2*)(base + (size_t)m * DIMM + nn) =
                    make_float2(acc[mi][ni][0], acc[mi][ni][1]);
                *(float2*)(base + (size_t)(m + 8) * DIMM + nn) =
                    make_float2(acc[mi][ni][2], acc[mi][ni][3]);
            }
        }
    }
}

__global__ void __launch_bounds__(128, 2)
gemm_qkv(const uint32_t* __restrict__ Ah, const uint32_t* __restrict__ Al,
         const uint32_t* __restrict__ Bqh, const uint32_t* __restrict__ Bql,
         const uint32_t* __restrict__ Bkh, const uint32_t* __restrict__ Bkl,
         const uint32_t* __restrict__ Bvh, const uint32_t* __restrict__ Bvl,
         uint32_t* __restrict__ Qh, uint32_t* __restrict__ Ql,
         uint32_t* __restrict__ Kh, uint32_t* __restrict__ Kl,
         uint32_t* __restrict__ Vh, uint32_t* __restrict__ Vl)
{
    __shared__ GSmem sm;
    const uint32_t *Bh, *Bl; uint32_t *Yh, *Yl; float sc_;
    if (blockIdx.z == 0)      { Bh = Bqh; Bl = Bql; Yh = Qh; Yl = Ql; sc_ = 0.125f; }
    else if (blockIdx.z == 1) { Bh = Bkh; Bl = Bkl; Yh = Kh; Yl = Kl; sc_ = 1.0f; }
    else                      { Bh = Bvh; Bl = Bvl; Yh = Vh; Yl = Vl; sc_ = 1.0f; }
    gemm_body(sm, Ah, Al, Bh, Bl, Yh, Yl, nullptr, nullptr, true, sc_);
}

__global__ void __launch_bounds__(128, 2)
gemm_o(const uint32_t* __restrict__ Ah, const uint32_t* __restrict__ Al,
       const uint32_t* __restrict__ Bh, const uint32_t* __restrict__ Bl,
       float* __restrict__ Y0, float* __restrict__ Y1)
{
    __shared__ GSmem sm;
    gemm_body(sm, Ah, Al, Bh, Bl, nullptr, nullptr, Y0, Y1, false, 1.0f);
}

// ---------------------------------------------------------------------------
// Flash attention bf16x3, register-resident softmax.
// 8 warps; each warp: 16 q-rows x 64 keys (scores) and 16 q-rows x 128 d (out).
// K double-buffered via cp.async; V single-buffered (PRMT repack).
// Q pre-scaled by 0.125 in the Q GEMM.
// ---------------------------------------------------------------------------
struct FSmem {
    uint32_t Qh[128][68], Ql[128][68];     // [q][d_pair]
    uint32_t Kh[2][64][68], Kl[2][64][68]; // [buf][key][d_pair]
    uint32_t Vh[32][136], Vl[32][136];     // [key_pair][d]
};

__global__ void __launch_bounds__(256, 1)
flash_bf16x3(const uint32_t* __restrict__ Qph, const uint32_t* __restrict__ Qpl,
             const uint32_t* __restrict__ Kph, const uint32_t* __restrict__ Kpl,
             const uint32_t* __restrict__ Vph, const uint32_t* __restrict__ Vpl,
             uint32_t* __restrict__ Aoh, uint32_t* __restrict__ Aol)
{
    extern __shared__ char raw[];
    FSmem& s = *reinterpret_cast<FSmem*>(raw);

    const int tid = threadIdx.x;
    const int w = tid >> 5, lane = tid & 31;
    const int grp = lane >> 2, tk = lane & 3;
    const int m0 = w * 16;
    const int bh = blockIdx.y;
    const int b = bh >> 4, h = bh & 15;
    const int qt = blockIdx.x;
    const size_t tokb = (size_t)b * SEQ;
    const int cph = h * 32;
    const int colr = h * HD;

    auto fillK = [&](int buf, int kt) {
        #pragma unroll
        for (int it = 0; it < 8; it++) {
            int task = tid + it * 256;        // 0..2047
            int t2 = task & 1023;
            int r = t2 >> 4, cj = t2 & 15;
            int jj = (cj < 8) ? (cph + cj * 4) : (512 + cph + (cj - 8) * 4);
            const uint32_t* src = (task < 1024 ? Kph : Kpl) + (tokb + kt * 64 + r) * KP + jj;
            if (task < 1024) cpa16(&s.Kh[buf][r][cj * 4], src);
            else             cpa16(&s.Kl[buf][r][cj * 4], src);
        }
        CP_COMMIT();
    };

    auto fillV = [&](int kt) {
        #pragma unroll
        for (int it = 0; it < 4; it++) {
            int task = tid + it * 256;        // 0..1023
            int t2 = task & 511;
            int p = t2 >> 4, cj = t2 & 15;
            int jj = (cj < 8) ? (cph + cj * 4) : (512 + cph + (cj - 8) * 4);
            int db = (cj < 8) ? (cj * 8) : (64 + (cj - 8) * 8);
            const uint32_t* base = (task < 512) ? Vph : Vpl;
            const uint32_t* r0 = base + (tokb + kt * 64 + 2 * p) * KP + jj;
            uint4 a4 = *(const uint4*)r0;
            uint4 b4 = *(const uint4*)(r0 + KP);
            uint32_t* dst = (task < 512) ? &s.Vh[p][db] : &s.Vl[p][db];
            dst[0] = __byte_perm(a4.x, b4.x, 0x5410);
            dst[1] = __byte_perm(a4.x, b4.x, 0x7632);
            dst[2] = __byte_perm(a4.y, b4.y, 0x5410);
            dst[3] = __byte_perm(a4.y, b4.y, 0x7632);
            dst[4] = __byte_perm(a4.z, b4.z, 0x5410);
            dst[5] = __byte_perm(a4.z, b4.z, 0x7632);
            dst[6] = __byte_perm(a4.w, b4.w, 0x5410);
            dst[7] = __byte_perm(a4.w, b4.w, 0x7632);
        }
    };

    // prologue: K0 async, Q direct, V0 direct
    fillK(0, 0);
    #pragma unroll
    for (int it = 0; it < 16; it++) {
        int task = tid + it * 256;            // 0..4095
        int t2 = task & 2047;
        int r = t2 >> 4, cj = t2 & 15;
        int jj = (cj < 8) ? (cph + cj * 4) : (512 + cph + (cj - 8) * 4);
        const uint32_t* src = (task < 2048 ? Qph : Qpl) + (tokb + qt * 128 + r) * KP + jj;
        uint4 v = *(const uint4*)src;
        uint32_t* dst = (task < 2048) ? &s.Qh[r][cj * 4] : &s.Ql[r][cj * 4];
        dst[0] = v.x; dst[1] = v.y; dst[2] = v.z; dst[3] = v.w;
    }
    fillV(0);
    asm volatile("cp.async.wait_group 0;\n" ::: "memory");
    __syncthreads();

    float m0f = -1e30f, m1f = -1e30f, l0f = 0.0f, l1f = 0.0f;
    float o[16][4];
    #pragma unroll
    for (int di = 0; di < 16; di++)
        #pragma unroll
        for (int v = 0; v < 4; v++) o[di][v] = 0.0f;

    for (int kt = 0; kt < SEQ / 64; kt++) {
        const int cur = kt & 1;
        if (kt + 1 < SEQ / 64) fillK(cur ^ 1, kt + 1);   // overlaps score compute

        // ---- scores: 16 q-rows x 64 keys, in registers ----
        float sc[8][4];
        #pragma unroll
        for (int ni = 0; ni < 8; ni++)
            #pragma unroll
            for (int v = 0; v < 4; v++) sc[ni][v] = 0.0f;

        #pragma unroll
        for (int kk = 0; kk < 8; kk++) {
            uint32_t afh[4], afl[4];
            afh[0] = s.Qh[m0 + grp    ][kk * 8 + tk    ];
            afh[1] = s.Qh[m0 + grp + 8][kk * 8 + tk    ];
            afh[2] = s.Qh[m0 + grp    ][kk * 8 + tk + 4];
            afh[3] = s.Qh[m0 + grp + 8][kk * 8 + tk + 4];
            afl[0] = s.Ql[m0 + grp    ][kk * 8 + tk    ];
            afl[1] = s.Ql[m0 + grp + 8][kk * 8 + tk    ];
            afl[2] = s.Ql[m0 + grp    ][kk * 8 + tk + 4];
            afl[3] = s.Ql[m0 + grp + 8][kk * 8 + tk + 4];
            #pragma unroll
            for (int ni = 0; ni < 8; ni++) {
                uint32_t bfh[2], bfl[2];
                bfh[0] = s.Kh[cur][ni * 8 + grp][kk * 8 + tk    ];
                bfh[1] = s.Kh[cur][ni * 8 + grp][kk * 8 + tk + 4];
                bfl[0] = s.Kl[cur][ni * 8 + grp][kk * 8 + tk    ];
                bfl[1] = s.Kl[cur][ni * 8 + grp][kk * 8 + tk + 4];
                mma16(sc[ni], afh, bfh);
                mma16(sc[ni], afh, bfl);
                mma16(sc[ni], afl, bfh);
            }
        }

        // ---- online softmax in registers (rows grp / grp+8; cols across tk) ----
        float mx0 = -1e30f, mx1 = -1e30f;
        #pragma unroll
        for (int ni = 0; ni < 8; ni++) {
            mx0 = fmaxf(mx0, fmaxf(sc[ni][0], sc[ni][1]));
            mx1 = fmaxf(mx1, fmaxf(sc[ni][2], sc[ni][3]));
        }
        mx0 = fmaxf(mx0, __shfl_xor_sync(0xffffffffu, mx0, 1));
        mx0 = fmaxf(mx0, __shfl_xor_sync(0xffffffffu, mx0, 2));
        mx1 = fmaxf(mx1, __shfl_xor_sync(0xffffffffu, mx1, 1));
        mx1 = fmaxf(mx1, __shfl_xor_sync(0xffffffffu, mx1, 2));
        float mn0 = fmaxf(m0f, mx0), mn1 = fmaxf(m1f, mx1);
        float al0 = __expf(m0f - mn0), al1 = __expf(m1f - mn1);
        m0f = mn0; m1f = mn1;
        float ls0 = 0.0f, ls1 = 0.0f;
        #pragma unroll
        for (int ni = 0; ni < 8; ni++) {
            sc[ni][0] = __expf(sc[ni][0] - mn0);
            sc[ni][1] = __expf(sc[ni][1] - mn0);
            sc[ni][2] = __expf(sc[ni][2] - mn1);
            sc[ni][3] = __expf(sc[ni][3] - mn1);
            ls0 += sc[ni][0] + sc[ni][1];
            ls1 += sc[ni][2] + sc[ni][3];
        }
        ls0 += __shfl_xor_sync(0xffffffffu, ls0, 1);
        ls0 += __shfl_xor_sync(0xffffffffu, ls0, 2);
        ls1 += __shfl_xor_sync(0xffffffffu, ls1, 1);
        ls1 += __shfl_xor_sync(0xffffffffu, ls1, 2);
        l0f = l0f * al0 + ls0;
        l1f = l1f * al1 + ls1;

        // ---- pack P as A-fragments (C layout == A layout) ----
        uint32_t pah[4][4], pal[4][4];
        #pragma unroll
        for (int sp = 0; sp < 4; sp++) {
            cvt2(sc[2 * sp    ][0], sc[2 * sp    ][1], pah[sp][0], pal[sp][0]);
            cvt2(sc[2 * sp    ][2], sc[2 * sp    ][3], pah[sp][1], pal[sp][1]);
            cvt2(sc[2 * sp + 1][0], sc[2 * sp + 1][1], pah[sp][2], pal[sp][2]);
            cvt2(sc[2 * sp + 1][2], sc[2 * sp + 1][3], pah[sp][3], pal[sp][3]);
        }

        // ---- rescale + PV ----
        #pragma unroll
        for (int di = 0; di < 16; di++) {
            o[di][0] *= al0; o[di][1] *= al0;
            o[di][2] *= al1; o[di][3] *= al1;
        }
        #pragma unroll
        for (int sp = 0; sp < 4; sp++) {
            #pragma unroll
            for (int di = 0; di < 16; di++) {
                uint32_t bfh[2], bfl[2];
                bfh[0] = s.Vh[sp * 8 + tk    ][di * 8 + grp];
                bfh[1] = s.Vh[sp * 8 + tk + 4][di * 8 + grp];
                bfl[0] = s.Vl[sp * 8 + tk    ][di * 8 + grp];
                bfl[1] = s.Vl[sp * 8 + tk + 4][di * 8 + grp];
                mma16(o[di], pah[sp], bfh);
                mma16(o[di], pah[sp], bfl);
                mma16(o[di], pal[sp], bfh);
            }
        }

        __syncthreads();                    // done reading V[cur] / K[cur]
        if (kt + 1 < SEQ / 64) {
            fillV(kt + 1);
            asm volatile("cp.async.wait_group 0;\n" ::: "memory");
            __syncthreads();                // V + K[next] visible
        }
    }

    // ---- finalize: packed hi/lo output for the O GEMM ----
    float li0 = 1.0f / l0f, li1 = 1.0f / l1f;
    int tok = b * SEQ + qt * 128;
    #pragma unroll
    for (int di = 0; di < 16; di++) {
        int c = di * 8 + tk * 2;
        int g = (c < HD) ? (colr + c) : (1024 + colr + (c - HD));
        int idx = g >> 1;
        uint32_t hh, ll;
        cvt2(o[di][0] * li0, o[di][1] * li0, hh, ll);
        Aoh[(size_t)(tok + m0 + grp) * KP + idx] = hh;
        Aol[(size_t)(tok + m0 + grp) * KP + idx] = ll;
        cvt2(o[di][2] * li1, o[di][3] * li1, hh, ll);
        Aoh[(size_t)(tok + m0 + grp + 8) * KP + idx] = hh;
        Aol[(size_t)(tok + m0 + grp + 8) * KP + idx] = ll;
    }
}

// ---------------------------------------------------------------------------
extern "C" void kernel_launch(void* const* d_in, const int* in_sizes, int n_in,
                              void* d_out, int out_size)
{
    const float* zr   = (const float*)d_in[0];
    const float* zi   = (const float*)d_in[1];
    const float* wq_r = (const float*)d_in[2];
    const float* wq_i = (const float*)d_in[3];
    const float* wk_r = (const float*)d_in[4];
    const float* wk_i = (const float*)d_in[5];
    const float* wv_r = (const float*)d_in[6];
    const float* wv_i = (const float*)d_in[7];
    const float* wo_r = (const float*)d_in[8];
    const float* wo_i = (const float*)d_in[9];

    uint32_t* sc = nullptr;
    cudaGetSymbolAddress((void**)&sc, g_scratch);
    uint32_t* Azh = sc + 0u  * MEGA;
    uint32_t* Azl = sc + 4u  * MEGA;
    uint32_t* Bqh = sc + 8u  * MEGA;  uint32_t* Bql = sc + 10u * MEGA;
    uint32_t* Bkh = sc + 12u * MEGA;  uint32_t* Bkl = sc + 14u * MEGA;
    uint32_t* Bvh = sc + 16u * MEGA;  uint32_t* Bvl = sc + 18u * MEGA;
    uint32_t* Boh = sc + 20u * MEGA;  uint32_t* Bol = sc + 22u * MEGA;
    uint32_t* Qh  = sc + 24u * MEGA;  uint32_t* Ql  = sc + 28u * MEGA;
    uint32_t* Kh  = sc + 32u * MEGA;  uint32_t* Kl  = sc + 36u * MEGA;
    uint32_t* Vh  = sc + 40u * MEGA;  uint32_t* Vl  = sc + 44u * MEGA;
    uint32_t* Aoh = sc + 48u * MEGA;  uint32_t* Aol = sc + 52u * MEGA;

    float* yr = (float*)d_out;
    float* yi = (float*)d_out + NTD;

    pack_x<<<(NTOK * KP) / 256, 256>>>(zr, zi, Azh, Azl);
    pack_w<<<(KP * 2048) / 256, 256>>>(wq_r, wq_i, Bqh, Bql);
    pack_w<<<(KP * 2048) / 256, 256>>>(wk_r, wk_i, Bkh, Bkl);
    pack_w<<<(KP * 2048) / 256, 256>>>(wv_r, wv_i, Bvh, Bvl);
    pack_w<<<(KP * 2048) / 256, 256>>>(wo_r, wo_i, Boh, Bol);

    dim3 qkv_grid(2048 / 128, NTOK / 128, 3);   // (16, 32, 3)
    gemm_qkv<<<qkv_grid, 128>>>(Azh, Azl, Bqh, Bql, Bkh, Bkl, Bvh, Bvl,
                                Qh, Ql, Kh, Kl, Vh, Vl);

    static const int kSmem = (int)sizeof(FSmem);
    cudaFuncSetAttribute(flash_bf16x3, cudaFuncAttributeMaxDynamicSharedMemorySize, kSmem);
    dim3 fgrid(SEQ / 128, BATCH * NH);          // (16, 32)
    flash_bf16x3<<<fgrid, 256, kSmem>>>(Qh, Ql, Kh, Kl, Vh, Vl, Aoh, Aol);

    dim3 ogrid(2048 / 128, NTOK / 128);         // (16, 32)
    gemm_o<<<ogrid, 128>>>(Aoh, Aol, Boh, Bol, yr, yi);
}